// round 1
// baseline (speedup 1.0000x reference)
#include <cuda_runtime.h>

namespace {
constexpr int Bn = 8, Cin = 32, Cout = 32, Hh = 512, Ww = 512, Md = 1024;
constexpr int TH = 16, TW = 16, SP = 20;          // smem tile pitch (18 + pad)
constexpr int SX_ELEMS = Cin * 18 * SP;            // input tile (with halo)
constexpr int SW_ELEMS = Cout * Cin * 9;           // weights
constexpr int SMEM_BYTES = (SX_ELEMS + SW_ELEMS) * 4;
}

__device__ float g_style[Bn * Cin];

// style[b][c] = dot(w[b,:], style_w[c,:]) + style_b[c]
__global__ void style_kernel(const float* __restrict__ w,
                             const float* __restrict__ sw,
                             const float* __restrict__ sb) {
    int t = threadIdx.x;          // 256 threads: (b, c)
    int b = t >> 5, c = t & 31;
    const float4* wv = reinterpret_cast<const float4*>(w + b * Md);
    const float4* sv = reinterpret_cast<const float4*>(sw + c * Md);
    float acc = 0.f;
#pragma unroll 4
    for (int i = 0; i < Md / 4; i++) {
        float4 a = wv[i], s = sv[i];
        acc += a.x * s.x + a.y * s.y + a.z * s.z + a.w * s.w;
    }
    g_style[t] = acc + sb[c];
}

__global__ __launch_bounds__(256, 2) void conv_kernel(
    const float* __restrict__ x, const float* __restrict__ kern,
    float* __restrict__ out) {
    extern __shared__ float smem[];
    float* sX = smem;             // [Cin][18][SP], premodulated input tile
    float* sW = smem + SX_ELEMS;  // [Cin*9][Cout]  (cout fastest -> conflict-free)

    const int b   = blockIdx.y;
    const int tx0 = (blockIdx.x & 31) * TW;
    const int ty0 = (blockIdx.x >> 5) * TH;
    const int tid = threadIdx.x;

    // ---- weights -> smem, transposed to [cin*9][cout] ----
    for (int i = tid; i < SW_ELEMS; i += 256) {
        int co  = i / (Cin * 9);
        int rem = i - co * (Cin * 9);
        sW[rem * Cout + co] = kern[i];
    }

    // ---- input tile with halo, premultiplied by per-(b,cin) style ----
    const float* xb = x + (size_t)b * Cin * Hh * Ww;
    for (int i = tid; i < Cin * 18 * 18; i += 256) {
        int c  = i / (18 * 18);
        int r  = i - c * (18 * 18);
        int iy = r / 18, ix = r - iy * 18;
        int gy = ty0 + iy - 1, gx = tx0 + ix - 1;
        float v = 0.f;
        if ((unsigned)gy < (unsigned)Hh && (unsigned)gx < (unsigned)Ww)
            v = xb[(size_t)c * (Hh * Ww) + gy * Ww + gx] * g_style[b * Cin + c];
        sX[c * (18 * SP) + iy * SP + ix] = v;
    }
    __syncthreads();

    // ---- each thread: one cout, 4x8 output sub-tile ----
    const int cout   = tid >> 3;
    const int region = tid & 7;
    const int oy0 = (region >> 1) * 4;    // {0,4,8,12}
    const int ox0 = (region & 1) * 8;     // {0,8}

    float acc[4][8];
#pragma unroll
    for (int r = 0; r < 4; r++)
#pragma unroll
        for (int q = 0; q < 8; q++) acc[r][q] = 0.f;

    for (int c = 0; c < Cin; c++) {
        float wr[9];
#pragma unroll
        for (int k = 0; k < 9; k++) wr[k] = sW[(c * 9 + k) * Cout + cout];
        const float* xrow = sX + c * (18 * SP) + oy0 * SP + ox0;
#pragma unroll
        for (int ir = 0; ir < 6; ir++) {
            float xv[10];
            float4 a4 = *reinterpret_cast<const float4*>(xrow + ir * SP);
            float4 b4 = *reinterpret_cast<const float4*>(xrow + ir * SP + 4);
            float2 c2 = *reinterpret_cast<const float2*>(xrow + ir * SP + 8);
            xv[0]=a4.x; xv[1]=a4.y; xv[2]=a4.z; xv[3]=a4.w;
            xv[4]=b4.x; xv[5]=b4.y; xv[6]=b4.z; xv[7]=b4.w;
            xv[8]=c2.x; xv[9]=c2.y;
#pragma unroll
            for (int kr = 0; kr < 3; kr++) {
                int orow = ir - kr;
                if (orow >= 0 && orow < 4) {
#pragma unroll
                    for (int oc = 0; oc < 8; oc++) {
#pragma unroll
                        for (int kc = 0; kc < 3; kc++)
                            acc[orow][oc] = fmaf(wr[kr * 3 + kc], xv[oc + kc],
                                                 acc[orow][oc]);
                    }
                }
            }
        }
    }

    // ---- store 4x8 per thread as 2x float4 per row ----
    float* ob = out + ((size_t)b * Cout + cout) * (Hh * Ww);
#pragma unroll
    for (int r = 0; r < 4; r++) {
        int gy = ty0 + oy0 + r;
        float* p = ob + (size_t)gy * Ww + tx0 + ox0;
        *reinterpret_cast<float4*>(p)     = make_float4(acc[r][0], acc[r][1],
                                                        acc[r][2], acc[r][3]);
        *reinterpret_cast<float4*>(p + 4) = make_float4(acc[r][4], acc[r][5],
                                                        acc[r][6], acc[r][7]);
    }
}

extern "C" void kernel_launch(void* const* d_in, const int* in_sizes, int n_in,
                              void* d_out, int out_size) {
    const float* x    = (const float*)d_in[0];
    const float* w    = (const float*)d_in[1];
    const float* kern = (const float*)d_in[2];
    const float* sw   = (const float*)d_in[3];
    const float* sb   = (const float*)d_in[4];
    float* out = (float*)d_out;

    cudaFuncSetAttribute(conv_kernel,
                         cudaFuncAttributeMaxDynamicSharedMemorySize, SMEM_BYTES);

    style_kernel<<<1, 256>>>(w, sw, sb);
    dim3 grid((Hh / TH) * (Ww / TW), Bn);
    conv_kernel<<<grid, 256, SMEM_BYTES>>>(x, kern, out);
}

// round 2
// speedup vs baseline: 2.4343x; 2.4343x over previous
#include <cuda_runtime.h>

namespace {
constexpr int Bn = 8, Cin = 32, Cout = 32, Hh = 512, Ww = 512, Md = 1024;
constexpr int TY = 16, TX = 16;          // CTA output tile (one b, all couts)
constexpr int SIP = 20;                  // sIn x pitch (18 + pad)
constexpr int SIN_ELEMS = Cin * 18 * SIP;   // 11520
constexpr int SWP = 40;                  // weight pitch: conflict-free B loads
constexpr int KTOT = Cin * 9;            // 288
constexpr int SW_ELEMS = KTOT * SWP;     // 11520
constexpr int LUT_OFF = SIN_ELEMS + SW_ELEMS;
constexpr int SMEM_WORDS = LUT_OFF + KTOT;
constexpr int SMEM_BYTES = SMEM_WORDS * 4;   // ~93.3 KB -> 2 CTAs/SM
}

__device__ float g_style[Bn * Cin];

__device__ __forceinline__ unsigned f2tf(float f) {
    unsigned u;
    asm("cvt.rna.tf32.f32 %0, %1;" : "=r"(u) : "f"(f));
    return u;
}

__device__ __forceinline__ void mma_tf32(float* d, const unsigned* a,
                                         const unsigned* b) {
    asm volatile(
        "mma.sync.aligned.m16n8k8.row.col.f32.tf32.tf32.f32 "
        "{%0,%1,%2,%3}, {%4,%5,%6,%7}, {%8,%9}, {%0,%1,%2,%3};\n"
        : "+f"(d[0]), "+f"(d[1]), "+f"(d[2]), "+f"(d[3])
        : "r"(a[0]), "r"(a[1]), "r"(a[2]), "r"(a[3]), "r"(b[0]), "r"(b[1]));
}

// style[b][c] = dot(w[b,:], style_w[c,:]) + style_b[c]
__global__ void style_kernel(const float* __restrict__ w,
                             const float* __restrict__ sw,
                             const float* __restrict__ sb) {
    int t = threadIdx.x;
    int b = t >> 5, c = t & 31;
    const float4* wv = reinterpret_cast<const float4*>(w + b * Md);
    const float4* sv = reinterpret_cast<const float4*>(sw + c * Md);
    float acc = 0.f;
#pragma unroll 4
    for (int i = 0; i < Md / 4; i++) {
        float4 a = wv[i], s = sv[i];
        acc += a.x * s.x + a.y * s.y + a.z * s.z + a.w * s.w;
    }
    g_style[t] = acc + sb[c];
}

__global__ __launch_bounds__(256, 2) void conv_mma_kernel(
    const float* __restrict__ x, const float* __restrict__ kern,
    float* __restrict__ out) {
    extern __shared__ unsigned smem[];
    unsigned* sIn  = smem;                  // [32][18][20] tf32, premodulated
    unsigned* sW   = smem + SIN_ELEMS;      // [288][40] tf32
    unsigned* lutA = smem + LUT_OFF;        // [288] base offsets into sIn

    const int b  = blockIdx.z;
    const int y0 = blockIdx.y * TY;
    const int x0 = blockIdx.x * TX;
    const int tid  = threadIdx.x;
    const int wrp  = tid >> 5;
    const int lane = tid & 31;
    const int g    = lane >> 2;   // 0..7
    const int tig  = lane & 3;    // 0..3

    // ---- LUT: k -> sIn offset (cin,ky,kx) ----
    for (int k = tid; k < KTOT; k += 256) {
        int c = k / 9, r = k - 9 * c, ky = r / 3, kx = r - 3 * ky;
        lutA[k] = c * (18 * SIP) + ky * SIP + kx;
    }
    // ---- weights -> sW[k][cout], tf32 ----
    for (int j = tid; j < Cout * KTOT; j += 256) {
        int co = j / KTOT, k = j - co * KTOT;
        sW[k * SWP + co] = f2tf(kern[j]);
    }
    // ---- input tile (18x18 halo per cin), premodulated, tf32 ----
    const float* xb = x + (size_t)b * Cin * (Hh * Ww);
    for (int i = tid; i < Cin * 18 * 18; i += 256) {
        int c = i / 324, r = i - c * 324, iy = r / 18, ix = r - iy * 18;
        int gy = y0 + iy - 1, gx = x0 + ix - 1;
        float v = 0.f;
        if ((unsigned)gy < (unsigned)Hh && (unsigned)gx < (unsigned)Ww)
            v = xb[(size_t)c * (Hh * Ww) + gy * Ww + gx] * g_style[b * Cin + c];
        sIn[c * (18 * SIP) + iy * SIP + ix] = f2tf(v);
    }
    __syncthreads();

    // ---- warp tile: M=32 (y rows 2w,2w+1 x 16 cols), N=32 (all couts) ----
    float d[2][4][4] = {};

#pragma unroll
    for (int kc = 0; kc < KTOT; kc += 8) {
        unsigned off0 = lutA[kc + tig];
        unsigned off4 = lutA[kc + tig + 4];
        unsigned a[2][4];
#pragma unroll
        for (int mt = 0; mt < 2; mt++) {
            int yb = (2 * wrp + mt) * SIP;
            a[mt][0] = sIn[off0 + yb + g];
            a[mt][1] = sIn[off0 + yb + g + 8];
            a[mt][2] = sIn[off4 + yb + g];
            a[mt][3] = sIn[off4 + yb + g + 8];
        }
        unsigned bf[4][2];
#pragma unroll
        for (int nt = 0; nt < 4; nt++) {
            bf[nt][0] = sW[(kc + tig) * SWP + nt * 8 + g];
            bf[nt][1] = sW[(kc + tig + 4) * SWP + nt * 8 + g];
        }
#pragma unroll
        for (int mt = 0; mt < 2; mt++)
#pragma unroll
            for (int nt = 0; nt < 4; nt++)
                mma_tf32(d[mt][nt], a[mt], bf[nt]);
    }

    // ---- epilogue: D row = x offset, D col = cout ----
#pragma unroll
    for (int mt = 0; mt < 2; mt++) {
        int yy = y0 + 2 * wrp + mt;
#pragma unroll
        for (int nt = 0; nt < 4; nt++) {
            int co = nt * 8 + 2 * tig;
            float* p0 = out + (((size_t)b * Cout + co) * Hh + yy) * Ww + x0;
            float* p1 = p0 + (size_t)Hh * Ww;   // cout+1
            p0[g]     = d[mt][nt][0];
            p1[g]     = d[mt][nt][1];
            p0[g + 8] = d[mt][nt][2];
            p1[g + 8] = d[mt][nt][3];
        }
    }
}

extern "C" void kernel_launch(void* const* d_in, const int* in_sizes, int n_in,
                              void* d_out, int out_size) {
    const float* x    = (const float*)d_in[0];
    const float* w    = (const float*)d_in[1];
    const float* kern = (const float*)d_in[2];
    const float* sw   = (const float*)d_in[3];
    const float* sb   = (const float*)d_in[4];
    float* out = (float*)d_out;

    cudaFuncSetAttribute(conv_mma_kernel,
                         cudaFuncAttributeMaxDynamicSharedMemorySize, SMEM_BYTES);

    style_kernel<<<1, 256>>>(w, sw, sb);
    dim3 grid(Ww / TX, Hh / TY, Bn);
    conv_mma_kernel<<<grid, 256, SMEM_BYTES>>>(x, kern, out);
}

// round 4
// speedup vs baseline: 2.7704x; 1.1380x over previous
#include <cuda_runtime.h>
#include <cstdint>

namespace {
constexpr int Md = 1024;
constexpr int TX = 32, TY = 12;
constexpr int NPY = TY + 2;            // 14 input rows
constexpr int XPITCH = 40;             // words per py row (slots 0..39)
constexpr int CPITCH = 568;            // 14*40=560 pad->568 (568%32==24)
constexpr int OFF_STY = 0;             // 32 floats
constexpr int OFF_W   = 32;            // 9*1024 words
constexpr int OFF_IN  = 32 + 9 * 1024; // 9248 (byte off 36992, 16B aligned)
constexpr int SMEM_WORDS = OFF_IN + 32 * CPITCH;   // 9248+18176=27424
constexpr int SMEM_BYTES = SMEM_WORDS * 4;         // 109696 -> 2 CTAs/SM
constexpr int HW = 512 * 512;
}

__device__ float g_style[8 * 32];

__device__ __forceinline__ unsigned f2tf(float f) {
    unsigned u; asm("cvt.rna.tf32.f32 %0, %1;" : "=r"(u) : "f"(f)); return u;
}
__device__ __forceinline__ void mma_tf32(float* d, const unsigned* a,
                                         const unsigned* b) {
    asm volatile(
        "mma.sync.aligned.m16n8k8.row.col.f32.tf32.tf32.f32 "
        "{%0,%1,%2,%3}, {%4,%5,%6,%7}, {%8,%9}, {%0,%1,%2,%3};\n"
        : "+f"(d[0]), "+f"(d[1]), "+f"(d[2]), "+f"(d[3])
        : "r"(a[0]), "r"(a[1]), "r"(a[2]), "r"(a[3]), "r"(b[0]), "r"(b[1]));
}

__global__ void style_kernel(const float* __restrict__ w,
                             const float* __restrict__ sw,
                             const float* __restrict__ sb) {
    int t = threadIdx.x, b = t >> 5, c = t & 31;
    const float4* wv = reinterpret_cast<const float4*>(w + b * Md);
    const float4* sv = reinterpret_cast<const float4*>(sw + c * Md);
    float acc = 0.f;
#pragma unroll 4
    for (int i = 0; i < Md / 4; i++) {
        float4 a = wv[i], s = sv[i];
        acc += a.x * s.x + a.y * s.y + a.z * s.z + a.w * s.w;
    }
    g_style[t] = acc + sb[c];
}

__global__ __launch_bounds__(256, 2) void conv_mma2(
    const float* __restrict__ x, const float* __restrict__ kern,
    float* __restrict__ out) {
    extern __shared__ unsigned sm[];
    float*    smf = reinterpret_cast<float*>(sm);
    unsigned* sW  = sm + OFF_W;
    unsigned* sIn = sm + OFF_IN;

    const int b  = blockIdx.z;
    const int y0 = blockIdx.y * TY;
    const int x0 = blockIdx.x * TX;
    const int tid = threadIdx.x;
    const int w = tid >> 5, lane = tid & 31;
    const int g = lane >> 2, tig = lane & 3;

    if (tid < 32) smf[OFF_STY + tid] = g_style[b * 32 + tid];
    __syncthreads();

    // ---- weights: sW[t][cin][cout ^ ((cin&3)<<3)], tf32 ----
    for (int j = tid; j < 9216; j += 256) {
        int co = j / 288, rr = j - co * 288;
        int cin = rr / 9, t9 = rr - cin * 9;
        sW[t9 * 1024 + cin * 32 + (co ^ ((cin & 3) << 3))] = f2tf(kern[j]);
    }

    // ---- input: sIn[c][py][slot], slot = gx - x0 + 4, premodulated tf32 ----
    for (int j = tid; j < 32 * NPY * 10; j += 256) {
        int c  = j / (NPY * 10);
        int r  = j - c * (NPY * 10);
        int py = r / 10, pxq = r - py * 10;
        int gy  = y0 - 1 + py;
        int gxq = x0 - 4 + 4 * pxq;
        float4 v = make_float4(0.f, 0.f, 0.f, 0.f);
        if ((unsigned)gy < 512u) {
            const float* row = x + ((size_t)(b * 32 + c)) * HW + (size_t)gy * 512;
            if (gxq >= 0 && gxq + 3 < 512) {
                v = *reinterpret_cast<const float4*>(row + gxq);
            } else {
#pragma unroll
                for (int i = 0; i < 4; i++) {
                    int gx = gxq + i;
                    if ((unsigned)gx < 512u)
                        reinterpret_cast<float*>(&v)[i] = row[gx];
                }
            }
        }
        float s = smf[OFF_STY + c];
        uint4 tv = make_uint4(f2tf(v.x * s), f2tf(v.y * s),
                              f2tf(v.z * s), f2tf(v.w * s));
        *reinterpret_cast<uint4*>(sIn + c * CPITCH + py * XPITCH + 4 * pxq) = tv;
    }
    __syncthreads();

    // ---- compute: warp handles m-tiles mu = w, w+8, w+16 ----
    int yr[3], xh[3];
#pragma unroll
    for (int mi = 0; mi < 3; mi++) {
        int mu = w + 8 * mi;
        yr[mi] = mu >> 1;
        xh[mi] = mu & 1;
    }

    float d[3][4][4];
#pragma unroll
    for (int mi = 0; mi < 3; mi++)
#pragma unroll
        for (int nt = 0; nt < 4; nt++)
#pragma unroll
            for (int q = 0; q < 4; q++) d[mi][nt][q] = 0.f;

    const int tigC = tig * CPITCH;
    int nx[4];
#pragma unroll
    for (int nt = 0; nt < 4; nt++) nx[nt] = tig * 32 + ((nt ^ tig) << 3) + g;

    for (int t = 0; t < 9; t++) {
        int ky = t / 3, kx = t - 3 * ky;
        int ab[3];
#pragma unroll
        for (int mi = 0; mi < 3; mi++)
            ab[mi] = (yr[mi] + ky) * XPITCH + xh[mi] * 16 + kx + 3 + g;
        const unsigned* bw = sW + t * 1024;

#pragma unroll
        for (int kc = 0; kc < 32; kc += 8) {
            unsigned a[3][4], bf[4][2];
            int ct = kc * CPITCH + tigC;
#pragma unroll
            for (int mi = 0; mi < 3; mi++) {
                a[mi][0] = sIn[ct + ab[mi]];
                a[mi][1] = sIn[ct + ab[mi] + 8];
                a[mi][2] = sIn[ct + 4 * CPITCH + ab[mi]];
                a[mi][3] = sIn[ct + 4 * CPITCH + ab[mi] + 8];
            }
#pragma unroll
            for (int nt = 0; nt < 4; nt++) {
                bf[nt][0] = bw[kc * 32 + nx[nt]];
                bf[nt][1] = bw[kc * 32 + 128 + nx[nt]];
            }
#pragma unroll
            for (int mi = 0; mi < 3; mi++)
#pragma unroll
                for (int nt = 0; nt < 4; nt++)
                    mma_tf32(d[mi][nt], a[mi], bf[nt]);
        }
    }

    // ---- epilogue ----
#pragma unroll
    for (int mi = 0; mi < 3; mi++) {
        int gy = y0 + yr[mi];
        if (gy < 512) {
#pragma unroll
            for (int nt = 0; nt < 4; nt++) {
                int co = nt * 8 + 2 * tig;
                float* p0 = out + ((size_t)(b * 32 + co)) * HW +
                            (size_t)gy * 512 + x0 + xh[mi] * 16;
                float* p1 = p0 + HW;
                p0[g]     = d[mi][nt][0];
                p1[g]     = d[mi][nt][1];
                p0[g + 8] = d[mi][nt][2];
                p1[g + 8] = d[mi][nt][3];
            }
        }
    }
}

extern "C" void kernel_launch(void* const* d_in, const int* in_sizes, int n_in,
                              void* d_out, int out_size) {
    const float* x    = (const float*)d_in[0];
    const float* wmap = (const float*)d_in[1];
    const float* kern = (const float*)d_in[2];
    const float* sw   = (const float*)d_in[3];
    const float* sbv  = (const float*)d_in[4];
    float* out = (float*)d_out;

    cudaFuncSetAttribute(conv_mma2,
                         cudaFuncAttributeMaxDynamicSharedMemorySize, SMEM_BYTES);
    style_kernel<<<1, 256>>>(wmap, sw, sbv);
    dim3 grid(512 / TX, (512 + TY - 1) / TY, 8);
    conv_mma2<<<grid, 256, SMEM_BYTES>>>(x, kern, out);
}

// round 5
// speedup vs baseline: 3.9430x; 1.4233x over previous
#include <cuda_runtime.h>
#include <cstdint>

namespace {
constexpr int Md = 1024;
constexpr int TX = 32, TY = 12;
constexpr int NPY = 14;               // input rows (halo)
constexpr int XP  = 40;               // words per py row
constexpr int CP  = 568;              // words per cin (14*40=560 pad->568, %32==24)
constexpr int CGW = 8 * CP;           // words per cin-group buffer (4544)
constexpr int OFF_IN = 9216;          // after weights
constexpr int SMEM_BYTES = (OFF_IN + 4 * CGW) * 4;   // 109568 -> 2 CTAs/SM
constexpr int HW = 512 * 512;
}

__device__ float g_style[8 * 32];

__device__ __forceinline__ unsigned f2tf(float f) {
    unsigned u; asm("cvt.rna.tf32.f32 %0, %1;" : "=r"(u) : "f"(f)); return u;
}
__device__ __forceinline__ uint32_t s2u(const void* p) {
    uint32_t a;
    asm("{ .reg .u64 t; cvta.to.shared.u64 t, %1; cvt.u32.u64 %0, t; }"
        : "=r"(a) : "l"(p));
    return a;
}
__device__ __forceinline__ void mma_tf32(float* d, const unsigned* a,
                                         const unsigned* b) {
    asm volatile(
        "mma.sync.aligned.m16n8k8.row.col.f32.tf32.tf32.f32 "
        "{%0,%1,%2,%3}, {%4,%5,%6,%7}, {%8,%9}, {%0,%1,%2,%3};\n"
        : "+f"(d[0]), "+f"(d[1]), "+f"(d[2]), "+f"(d[3])
        : "r"(a[0]), "r"(a[1]), "r"(a[2]), "r"(a[3]), "r"(b[0]), "r"(b[1]));
}
__device__ __forceinline__ void cp_wait(int n) {
    switch (n) {
        case 0: asm volatile("cp.async.wait_group 0;" ::: "memory"); break;
        case 1: asm volatile("cp.async.wait_group 1;" ::: "memory"); break;
        case 2: asm volatile("cp.async.wait_group 2;" ::: "memory"); break;
        default: asm volatile("cp.async.wait_group 3;" ::: "memory"); break;
    }
}

__global__ void style_kernel(const float* __restrict__ w,
                             const float* __restrict__ sw,
                             const float* __restrict__ sb) {
    int t = threadIdx.x, b = t >> 5, c = t & 31;
    const float4* wv = reinterpret_cast<const float4*>(w + b * Md);
    const float4* sv = reinterpret_cast<const float4*>(sw + c * Md);
    float acc = 0.f;
#pragma unroll 4
    for (int i = 0; i < Md / 4; i++) {
        float4 a = wv[i], s = sv[i];
        acc += a.x * s.x + a.y * s.y + a.z * s.z + a.w * s.w;
    }
    g_style[t] = acc + sb[c];
}

__global__ __launch_bounds__(256, 2) void conv_mma3(
    const float* __restrict__ x, const float* __restrict__ kern,
    float* __restrict__ out) {
    extern __shared__ unsigned sm[];
    unsigned* sW  = sm;            // [9][32 cin][32 cout ^ swz], tf32, modulated
    unsigned* sIn = sm + OFF_IN;   // [4 cg][8 cin][14 py][40], raw f32

    const int b  = blockIdx.z;
    const int y0 = blockIdx.y * TY;
    const int x0 = blockIdx.x * TX;
    const int tid = threadIdx.x;
    const int w = tid >> 5, lane = tid & 31;
    const int g = lane >> 2, tig = lane & 3;

    // ---- issue all 4 cin-group stages as cp.async groups ----
    const uint32_t sIn_b = s2u(sIn);
    const float* xb = x + (size_t)b * 32 * HW;
#pragma unroll
    for (int cg = 0; cg < 4; cg++) {
#pragma unroll
        for (int base = 0; base < 1120; base += 256) {
            int idx = base + tid;
            if (idx < 1120) {
                int c  = idx / 140;
                int r  = idx - 140 * c;
                int py = r / 10, j = r - 10 * py;
                int gy = y0 - 1 + py, gxq = x0 - 4 + 4 * j;
                bool ok = ((unsigned)gy < 512u) & (gxq >= 0) & (gxq <= 508);
                const float* gsrc = xb + ((size_t)(cg * 8 + c)) * HW +
                                    (size_t)(ok ? gy : 0) * 512 + (ok ? gxq : 0);
                unsigned zf = ok ? 16u : 0u;
                uint32_t sa = sIn_b +
                              ((unsigned)(cg * CGW + c * CP + py * XP + 4 * j) << 2);
                asm volatile("cp.async.cg.shared.global [%0], [%1], 16, %2;"
                             :: "r"(sa), "l"(gsrc), "r"(zf) : "memory");
            }
        }
        asm volatile("cp.async.commit_group;" ::: "memory");
    }

    // ---- build per-batch modulated tf32 weights (overlaps cp.async flight) ----
    for (int j = tid; j < 9216; j += 256) {
        int co = j / 288, rr = j - co * 288;
        int cin = rr / 9, t9 = rr - cin * 9;
        float v = kern[j] * g_style[b * 32 + cin];
        sW[t9 * 1024 + cin * 32 + (co ^ ((cin & 3) << 3))] = f2tf(v);
    }

    // ---- per-warp m-tiles ----
    int yr[3], xh[3];
#pragma unroll
    for (int mi = 0; mi < 3; mi++) {
        int mu = w + 8 * mi;
        yr[mi] = mu >> 1;
        xh[mi] = mu & 1;
    }
    int nxo[4];
#pragma unroll
    for (int nt = 0; nt < 4; nt++) nxo[nt] = ((nt ^ tig) << 3) + g;

    float d[3][4][4];
#pragma unroll
    for (int mi = 0; mi < 3; mi++)
#pragma unroll
        for (int nt = 0; nt < 4; nt++)
#pragma unroll
            for (int q = 0; q < 4; q++) d[mi][nt][q] = 0.f;

    // ---- pipelined compute over 4 cin-groups ----
#pragma unroll
    for (int cg = 0; cg < 4; cg++) {
        cp_wait(3 - cg);
        __syncthreads();
        const unsigned* buf = sIn + cg * CGW;
#pragma unroll
        for (int t = 0; t < 9; t++) {
            int ky = t / 3, kx = t - 3 * ky;
            unsigned a[3][4];
#pragma unroll
            for (int mi = 0; mi < 3; mi++) {
                int ao = tig * CP + (yr[mi] + ky) * XP + xh[mi] * 16 + kx + 3 + g;
                a[mi][0] = buf[ao];
                a[mi][1] = buf[ao + 8];
                a[mi][2] = buf[ao + 4 * CP];
                a[mi][3] = buf[ao + 4 * CP + 8];
            }
            unsigned bf[4][2];
            const unsigned* bw = sW + t * 1024 + (cg * 8 + tig) * 32;
#pragma unroll
            for (int nt = 0; nt < 4; nt++) {
                bf[nt][0] = bw[nxo[nt]];
                bf[nt][1] = bw[128 + nxo[nt]];
            }
#pragma unroll
            for (int mi = 0; mi < 3; mi++)
#pragma unroll
                for (int nt = 0; nt < 4; nt++)
                    mma_tf32(d[mi][nt], a[mi], bf[nt]);
        }
    }

    // ---- epilogue ----
#pragma unroll
    for (int mi = 0; mi < 3; mi++) {
        int gy = y0 + yr[mi];
        if (gy < 512) {
#pragma unroll
            for (int nt = 0; nt < 4; nt++) {
                int co = nt * 8 + 2 * tig;
                float* p0 = out + ((size_t)(b * 32 + co)) * HW +
                            (size_t)gy * 512 + x0 + xh[mi] * 16;
                float* p1 = p0 + HW;
                p0[g]     = d[mi][nt][0];
                p1[g]     = d[mi][nt][1];
                p0[g + 8] = d[mi][nt][2];
                p1[g + 8] = d[mi][nt][3];
            }
        }
    }
}

extern "C" void kernel_launch(void* const* d_in, const int* in_sizes, int n_in,
                              void* d_out, int out_size) {
    const float* x    = (const float*)d_in[0];
    const float* wmap = (const float*)d_in[1];
    const float* kern = (const float*)d_in[2];
    const float* sw   = (const float*)d_in[3];
    const float* sbv  = (const float*)d_in[4];
    float* out = (float*)d_out;

    cudaFuncSetAttribute(conv_mma3,
                         cudaFuncAttributeMaxDynamicSharedMemorySize, SMEM_BYTES);
    style_kernel<<<1, 256>>>(wmap, sw, sbv);
    dim3 grid(512 / TX, (512 + TY - 1) / TY, 8);
    conv_mma3<<<grid, 256, SMEM_BYTES>>>(x, kern, out);
}

// round 6
// speedup vs baseline: 4.8579x; 1.2320x over previous
#include <cuda_runtime.h>
#include <cstdint>

namespace {
constexpr int Md = 1024;
constexpr int TX = 32, TY = 12;
constexpr int XP  = 40;               // words per py row
constexpr int CP  = 568;              // words per cin (14*40=560 pad->568, %32==24)
constexpr int CGW = 8 * CP;           // words per cin-group buffer (4544)
constexpr int OFF_IN = 9216;          // after weights
constexpr int SMEM_BYTES = (OFF_IN + 4 * CGW) * 4;   // 109568 -> 2 CTAs/SM
constexpr int HW = 512 * 512;
}

__device__ float    g_style[8 * 32];
__device__ unsigned g_wmod[8 * 9216];   // [b][tap][cin][cout^swz], modulated tf32

__device__ __forceinline__ unsigned f2tf(float f) {
    unsigned u; asm("cvt.rna.tf32.f32 %0, %1;" : "=r"(u) : "f"(f)); return u;
}
__device__ __forceinline__ uint32_t s2u(const void* p) {
    uint32_t a;
    asm("{ .reg .u64 t; cvta.to.shared.u64 t, %1; cvt.u32.u64 %0, t; }"
        : "=r"(a) : "l"(p));
    return a;
}
__device__ __forceinline__ void mma_tf32(float* d, const unsigned* a,
                                         const unsigned* b) {
    asm volatile(
        "mma.sync.aligned.m16n8k8.row.col.f32.tf32.tf32.f32 "
        "{%0,%1,%2,%3}, {%4,%5,%6,%7}, {%8,%9}, {%0,%1,%2,%3};\n"
        : "+f"(d[0]), "+f"(d[1]), "+f"(d[2]), "+f"(d[3])
        : "r"(a[0]), "r"(a[1]), "r"(a[2]), "r"(a[3]), "r"(b[0]), "r"(b[1]));
}
__device__ __forceinline__ void cp_wait(int n) {
    switch (n) {
        case 0: asm volatile("cp.async.wait_group 0;" ::: "memory"); break;
        case 1: asm volatile("cp.async.wait_group 1;" ::: "memory"); break;
        case 2: asm volatile("cp.async.wait_group 2;" ::: "memory"); break;
        default: asm volatile("cp.async.wait_group 3;" ::: "memory"); break;
    }
}

__global__ void style_kernel(const float* __restrict__ w,
                             const float* __restrict__ sw,
                             const float* __restrict__ sb) {
    int t = threadIdx.x, b = t >> 5, c = t & 31;
    const float4* wv = reinterpret_cast<const float4*>(w + b * Md);
    const float4* sv = reinterpret_cast<const float4*>(sw + c * Md);
    float acc = 0.f;
#pragma unroll 4
    for (int i = 0; i < Md / 4; i++) {
        float4 a = wv[i], s = sv[i];
        acc += a.x * s.x + a.y * s.y + a.z * s.z + a.w * s.w;
    }
    g_style[t] = acc + sb[c];
}

// g_wmod[b][t9*1024 + cin*32 + (co ^ ((cin&3)<<3))] = tf32(kern[co][cin][t9]*style)
__global__ void modw_kernel(const float* __restrict__ kern) {
    int i = blockIdx.x * 256 + threadIdx.x;       // 0 .. 73727
    int b = i / 9216, j = i - b * 9216;
    int t9 = j >> 10, r = j & 1023;
    int cin = r >> 5, co = (r & 31) ^ ((cin & 3) << 3);
    g_wmod[i] = f2tf(kern[co * 288 + cin * 9 + t9] * g_style[b * 32 + cin]);
}

__global__ __launch_bounds__(256, 2) void conv_mma4(
    const float* __restrict__ x, float* __restrict__ out) {
    extern __shared__ unsigned sm[];
    unsigned* sW  = sm;            // [9][32 cin][32 cout ^ swz], tf32, modulated
    unsigned* sIn = sm + OFF_IN;   // [4 cg][8 cin][14 py][40], raw f32

    const int b  = blockIdx.z;
    const int y0 = blockIdx.y * TY;
    const int x0 = blockIdx.x * TX;
    const int tid = threadIdx.x;
    const int w = tid >> 5, lane = tid & 31;
    const int g = lane >> 2, tig = lane & 3;

    // ---- group 0: weights (premodulated tf32, fragment-ready layout) ----
    const uint32_t sW_b = s2u(sW);
    const unsigned* wsrc = g_wmod + b * 9216;
#pragma unroll
    for (int q = 0; q < 9; q++) {
        int idx = q * 256 + tid;                  // 0..2303 (x16B = 36864B)
        asm volatile("cp.async.cg.shared.global [%0], [%1], 16;"
                     :: "r"(sW_b + (unsigned)(idx * 16)),
                        "l"(wsrc + idx * 4) : "memory");
    }
    asm volatile("cp.async.commit_group;" ::: "memory");

    // ---- groups 1-4: activation cin-groups ----
    const uint32_t sIn_b = s2u(sIn);
    const float* xb = x + (size_t)b * 32 * HW;
#pragma unroll
    for (int cg = 0; cg < 4; cg++) {
#pragma unroll
        for (int base = 0; base < 1120; base += 256) {
            int idx = base + tid;
            if (idx < 1120) {
                int c  = idx / 140;
                int r  = idx - 140 * c;
                int py = r / 10, j = r - 10 * py;
                int gy = y0 - 1 + py, gxq = x0 - 4 + 4 * j;
                bool ok = ((unsigned)gy < 512u) & (gxq >= 0) & (gxq <= 508);
                const float* gsrc = xb + ((size_t)(cg * 8 + c)) * HW +
                                    (size_t)(ok ? gy : 0) * 512 + (ok ? gxq : 0);
                unsigned zf = ok ? 16u : 0u;
                uint32_t sa = sIn_b +
                              ((unsigned)(cg * CGW + c * CP + py * XP + 4 * j) << 2);
                asm volatile("cp.async.cg.shared.global [%0], [%1], 16, %2;"
                             :: "r"(sa), "l"(gsrc), "r"(zf) : "memory");
            }
        }
        asm volatile("cp.async.commit_group;" ::: "memory");
    }

    // ---- per-warp tile: 3 y-adjacent m-tiles (rows yb..yb+2), N=32 ----
    const int xh = w & 1;
    const int yb = (w >> 1) * 3;
    int nxo[4];
#pragma unroll
    for (int nt = 0; nt < 4; nt++) nxo[nt] = ((nt ^ tig) << 3) + g;

    float d[3][4][4];
#pragma unroll
    for (int mi = 0; mi < 3; mi++)
#pragma unroll
        for (int nt = 0; nt < 4; nt++)
#pragma unroll
            for (int q = 0; q < 4; q++) d[mi][nt][q] = 0.f;

    const unsigned* bw0 = sW + (tig) * 32;   // + cg*256 + t*1024

    for (int cg = 0; cg < 4; cg++) {
        cp_wait(3 - cg);
        __syncthreads();
        const unsigned* buf = sIn + cg * CGW;
        const unsigned* bw  = bw0 + cg * 256;          // (cg*8+tig)*32
#pragma unroll
        for (int kx = 0; kx < 3; kx++) {
            // 5 shared A fragments cover all (mi,ky): frag index = mi+ky
            unsigned fa[5][4];
#pragma unroll
            for (int p = 0; p < 5; p++) {
                int ao = tig * CP + (yb + p) * XP + xh * 16 + kx + 3 + g;
                fa[p][0] = buf[ao];
                fa[p][1] = buf[ao + 8];
                fa[p][2] = buf[ao + 4 * CP];
                fa[p][3] = buf[ao + 4 * CP + 8];
            }
#pragma unroll
            for (int ky = 0; ky < 3; ky++) {
                const unsigned* bt = bw + (ky * 3 + kx) * 1024;
                unsigned bf[4][2];
#pragma unroll
                for (int nt = 0; nt < 4; nt++) {
                    bf[nt][0] = bt[nxo[nt]];
                    bf[nt][1] = bt[128 + nxo[nt]];
                }
#pragma unroll
                for (int mi = 0; mi < 3; mi++)
#pragma unroll
                    for (int nt = 0; nt < 4; nt++)
                        mma_tf32(d[mi][nt], fa[mi + ky], bf[nt]);
            }
        }
    }

    // ---- epilogue ----
#pragma unroll
    for (int mi = 0; mi < 3; mi++) {
        int gy = y0 + yb + mi;
        if (gy < 512) {
#pragma unroll
            for (int nt = 0; nt < 4; nt++) {
                int co = nt * 8 + 2 * tig;
                float* p0 = out + ((size_t)(b * 32 + co)) * HW +
                            (size_t)gy * 512 + x0 + xh * 16;
                float* p1 = p0 + HW;
                p0[g]     = d[mi][nt][0];
                p1[g]     = d[mi][nt][1];
                p0[g + 8] = d[mi][nt][2];
                p1[g + 8] = d[mi][nt][3];
            }
        }
    }
}

extern "C" void kernel_launch(void* const* d_in, const int* in_sizes, int n_in,
                              void* d_out, int out_size) {
    const float* x    = (const float*)d_in[0];
    const float* wmap = (const float*)d_in[1];
    const float* kern = (const float*)d_in[2];
    const float* sw   = (const float*)d_in[3];
    const float* sbv  = (const float*)d_in[4];
    float* out = (float*)d_out;

    cudaFuncSetAttribute(conv_mma4,
                         cudaFuncAttributeMaxDynamicSharedMemorySize, SMEM_BYTES);
    style_kernel<<<1, 256>>>(wmap, sw, sbv);
    modw_kernel<<<288, 256>>>(kern);
    dim3 grid(512 / TX, (512 + TY - 1) / TY, 8);
    conv_mma4<<<grid, 256, SMEM_BYTES>>>(x, out);
}

// round 7
// speedup vs baseline: 5.9775x; 1.2305x over previous
#include <cuda_runtime.h>
#include <cstdint>

namespace {
constexpr int Md = 1024;
constexpr int TX = 32, TY = 12;
constexpr int XP  = 40;               // words per py row
constexpr int CP  = 568;              // words per cin (14*40=560 pad->568, %32==24)
constexpr int CGW = 8 * CP;           // words per cin-group buffer (4544)
constexpr int OFF_IN = 9216;          // after weights
constexpr int SMEM_BYTES = (OFF_IN + 4 * CGW) * 4;   // 109568 -> 2 CTAs/SM
constexpr int HW = 512 * 512;
}

__device__ float    g_style[8 * 32];
__device__ unsigned g_wmod[8 * 9216];   // [b][tap][cin][cout^swz], modulated tf32

__device__ __forceinline__ unsigned f2tf(float f) {
    unsigned u; asm("cvt.rna.tf32.f32 %0, %1;" : "=r"(u) : "f"(f)); return u;
}
__device__ __forceinline__ uint32_t s2u(const void* p) {
    uint32_t a;
    asm("{ .reg .u64 t; cvta.to.shared.u64 t, %1; cvt.u32.u64 %0, t; }"
        : "=r"(a) : "l"(p));
    return a;
}
__device__ __forceinline__ void mma_tf32(float* d, const unsigned* a,
                                         const unsigned* b) {
    asm volatile(
        "mma.sync.aligned.m16n8k8.row.col.f32.tf32.tf32.f32 "
        "{%0,%1,%2,%3}, {%4,%5,%6,%7}, {%8,%9}, {%0,%1,%2,%3};\n"
        : "+f"(d[0]), "+f"(d[1]), "+f"(d[2]), "+f"(d[3])
        : "r"(a[0]), "r"(a[1]), "r"(a[2]), "r"(a[3]), "r"(b[0]), "r"(b[1]));
}
__device__ __forceinline__ void cp_wait(int n) {
    switch (n) {
        case 0: asm volatile("cp.async.wait_group 0;" ::: "memory"); break;
        case 1: asm volatile("cp.async.wait_group 1;" ::: "memory"); break;
        case 2: asm volatile("cp.async.wait_group 2;" ::: "memory"); break;
        default: asm volatile("cp.async.wait_group 3;" ::: "memory"); break;
    }
}

// one block per (b,c): 128 threads x 8 elems, warp + smem reduce
__global__ void style_kernel(const float* __restrict__ w,
                             const float* __restrict__ sw,
                             const float* __restrict__ sb) {
    __shared__ float red[4];
    const int p = blockIdx.x, b = p >> 5, c = p & 31;
    const int t = threadIdx.x;
    const float4* wv = reinterpret_cast<const float4*>(w + b * Md) + 2 * t;
    const float4* sv = reinterpret_cast<const float4*>(sw + c * Md) + 2 * t;
    float4 a0 = wv[0], s0 = sv[0], a1 = wv[1], s1 = sv[1];
    float acc = a0.x * s0.x + a0.y * s0.y + a0.z * s0.z + a0.w * s0.w +
                a1.x * s1.x + a1.y * s1.y + a1.z * s1.z + a1.w * s1.w;
#pragma unroll
    for (int o = 16; o > 0; o >>= 1)
        acc += __shfl_xor_sync(0xFFFFFFFFu, acc, o);
    if ((t & 31) == 0) red[t >> 5] = acc;
    __syncthreads();
    if (t == 0) g_style[p] = red[0] + red[1] + red[2] + red[3] + sb[c];
}

// g_wmod[b][t9*1024 + cin*32 + (co ^ ((cin&3)<<3))] = tf32(kern[co][cin][t9]*style)
__global__ void modw_kernel(const float* __restrict__ kern) {
    int i = blockIdx.x * 256 + threadIdx.x;       // 0 .. 73727
    int b = i / 9216, j = i - b * 9216;
    int t9 = j >> 10, r = j & 1023;
    int cin = r >> 5, co = (r & 31) ^ ((cin & 3) << 3);
    g_wmod[i] = f2tf(kern[co * 288 + cin * 9 + t9] * g_style[b * 32 + cin]);
}

__global__ __launch_bounds__(256, 2) void conv_mma4(
    const float* __restrict__ x, float* __restrict__ out) {
    extern __shared__ unsigned sm[];
    unsigned* sW  = sm;            // [9][32 cin][32 cout ^ swz], tf32, modulated
    unsigned* sIn = sm + OFF_IN;   // [4 cg][8 cin][14 py][40], raw f32

    const int b  = blockIdx.z;
    const int y0 = blockIdx.y * TY;
    const int x0 = blockIdx.x * TX;
    const int tid = threadIdx.x;
    const int w = tid >> 5, lane = tid & 31;
    const int g = lane >> 2, tig = lane & 3;

    // ---- group 0: weights (premodulated tf32, fragment-ready layout) ----
    const uint32_t sW_b = s2u(sW);
    const unsigned* wsrc = g_wmod + b * 9216;
#pragma unroll
    for (int q = 0; q < 9; q++) {
        int idx = q * 256 + tid;                  // 0..2303 (x16B = 36864B)
        asm volatile("cp.async.cg.shared.global [%0], [%1], 16;"
                     :: "r"(sW_b + (unsigned)(idx * 16)),
                        "l"(wsrc + idx * 4) : "memory");
    }
    asm volatile("cp.async.commit_group;" ::: "memory");

    // ---- groups 1-4: activation cin-groups ----
    const uint32_t sIn_b = s2u(sIn);
    const float* xb = x + (size_t)b * 32 * HW;
#pragma unroll
    for (int cg = 0; cg < 4; cg++) {
#pragma unroll
        for (int base = 0; base < 1120; base += 256) {
            int idx = base + tid;
            if (idx < 1120) {
                int c  = idx / 140;
                int r  = idx - 140 * c;
                int py = r / 10, j = r - 10 * py;
                int gy = y0 - 1 + py, gxq = x0 - 4 + 4 * j;
                bool ok = ((unsigned)gy < 512u) & (gxq >= 0) & (gxq <= 508);
                const float* gsrc = xb + ((size_t)(cg * 8 + c)) * HW +
                                    (size_t)(ok ? gy : 0) * 512 + (ok ? gxq : 0);
                unsigned zf = ok ? 16u : 0u;
                uint32_t sa = sIn_b +
                              ((unsigned)(cg * CGW + c * CP + py * XP + 4 * j) << 2);
                asm volatile("cp.async.cg.shared.global [%0], [%1], 16, %2;"
                             :: "r"(sa), "l"(gsrc), "r"(zf) : "memory");
            }
        }
        asm volatile("cp.async.commit_group;" ::: "memory");
    }

    // ---- per-warp tile: 3 y-adjacent m-tiles (rows yb..yb+2), N=32 ----
    const int xh = w & 1;
    const int yb = (w >> 1) * 3;
    int nxo[4];
#pragma unroll
    for (int nt = 0; nt < 4; nt++) nxo[nt] = ((nt ^ tig) << 3) + g;

    float d[3][4][4];
#pragma unroll
    for (int mi = 0; mi < 3; mi++)
#pragma unroll
        for (int nt = 0; nt < 4; nt++)
#pragma unroll
            for (int q = 0; q < 4; q++) d[mi][nt][q] = 0.f;

    const unsigned* bw0 = sW + (tig) * 32;   // + cg*256 + t*1024

    for (int cg = 0; cg < 4; cg++) {
        cp_wait(3 - cg);
        __syncthreads();
        const unsigned* buf = sIn + cg * CGW;
        const unsigned* bw  = bw0 + cg * 256;          // (cg*8+tig)*32
#pragma unroll
        for (int kx = 0; kx < 3; kx++) {
            // 5 shared A fragments cover all (mi,ky): frag index = mi+ky
            unsigned fa[5][4];
#pragma unroll
            for (int p = 0; p < 5; p++) {
                int ao = tig * CP + (yb + p) * XP + xh * 16 + kx + 3 + g;
                fa[p][0] = buf[ao];
                fa[p][1] = buf[ao + 8];
                fa[p][2] = buf[ao + 4 * CP];
                fa[p][3] = buf[ao + 4 * CP + 8];
            }
#pragma unroll
            for (int ky = 0; ky < 3; ky++) {
                const unsigned* bt = bw + (ky * 3 + kx) * 1024;
                unsigned bf[4][2];
#pragma unroll
                for (int nt = 0; nt < 4; nt++) {
                    bf[nt][0] = bt[nxo[nt]];
                    bf[nt][1] = bt[128 + nxo[nt]];
                }
#pragma unroll
                for (int mi = 0; mi < 3; mi++)
#pragma unroll
                    for (int nt = 0; nt < 4; nt++)
                        mma_tf32(d[mi][nt], fa[mi + ky], bf[nt]);
            }
        }
    }

    // ---- epilogue ----
#pragma unroll
    for (int mi = 0; mi < 3; mi++) {
        int gy = y0 + yb + mi;
        if (gy < 512) {
#pragma unroll
            for (int nt = 0; nt < 4; nt++) {
                int co = nt * 8 + 2 * tig;
                float* p0 = out + ((size_t)(b * 32 + co)) * HW +
                            (size_t)gy * 512 + x0 + xh * 16;
                float* p1 = p0 + HW;
                p0[g]     = d[mi][nt][0];
                p1[g]     = d[mi][nt][1];
                p0[g + 8] = d[mi][nt][2];
                p1[g + 8] = d[mi][nt][3];
            }
        }
    }
}

extern "C" void kernel_launch(void* const* d_in, const int* in_sizes, int n_in,
                              void* d_out, int out_size) {
    const float* x    = (const float*)d_in[0];
    const float* wmap = (const float*)d_in[1];
    const float* kern = (const float*)d_in[2];
    const float* sw   = (const float*)d_in[3];
    const float* sbv  = (const float*)d_in[4];
    float* out = (float*)d_out;

    cudaFuncSetAttribute(conv_mma4,
                         cudaFuncAttributeMaxDynamicSharedMemorySize, SMEM_BYTES);
    style_kernel<<<256, 128>>>(wmap, sw, sbv);
    modw_kernel<<<288, 256>>>(kern);
    dim3 grid(512 / TX, (512 + TY - 1) / TY, 8);
    conv_mma4<<<grid, 256, SMEM_BYTES>>>(x, out);
}